// round 2
// baseline (speedup 1.0000x reference)
#include <cuda_runtime.h>
#include <cuda_bf16.h>

// SignatureEncoder: depth-2 path signature, x (128,16,1000,18) fp32.
// Reformulated without the scan:
//   m_i(t) = 0.5*(x_i(t)+x_i(t+1)) - x_i(0),  d_j(t) = x_j(t+1)-x_j(t)
//   S2_ij = sum_t m_i(t) d_j(t),   S1_i = x_i(T-1)-x_i(0)
// Channels: 0 = time (linspace(0,1,1000)), 1..18 = data. C=19, padded to 20.

#define TT      128          // time steps per tile
#define NTILE   8            // 8*128 = 1024 >= 999 steps (tail zero-padded)
#define CPAD    20
#define THREADS 256
#define NSTEPS  999
#define TROW    18           // input channels per time row
#define SEQLEN  18000        // 1000*18 floats per sequence

__device__ __forceinline__ unsigned long long pk2(float lo, float hi) {
    unsigned long long r;
    asm("mov.b64 %0, {%1,%2};" : "=l"(r) : "f"(lo), "f"(hi));
    return r;
}
__device__ __forceinline__ void up2(unsigned long long v, float& lo, float& hi) {
    asm("mov.b64 {%0,%1}, %2;" : "=f"(lo), "=f"(hi) : "l"(v));
}
__device__ __forceinline__ void ffma2(unsigned long long& a, unsigned long long x,
                                      unsigned long long y) {
    asm("fma.rn.f32x2 %0, %1, %2, %0;" : "+l"(a) : "l"(x), "l"(y));
}

__global__ __launch_bounds__(THREADS)
void sig2_kernel(const float* __restrict__ x, float* __restrict__ out) {
    const int n = blockIdx.x;
    const float* Xn = x + (size_t)n * SEQLEN;

    __shared__ __align__(16) float sm[2 * TT * CPAD];  // m tile then d tile; reused for reduction
    __shared__ float x0_s[CPAD];

    float* m_s = sm;
    float* d_s = sm + TT * CPAD;

    const int tid  = threadIdx.x;
    const int w    = tid >> 5;
    const int lane = tid & 31;
    const float INV = 1.0f / 999.0f;

    if (tid < 18)  x0_s[tid + 1] = Xn[tid];
    if (tid == 18) x0_s[0]  = 0.0f;
    if (tid == 19) x0_s[19] = 0.0f;
    __syncthreads();

    // 4x4 register tile per active lane (25 active lanes per warp cover 20x20)
    unsigned long long acc[4][2];
#pragma unroll
    for (int i = 0; i < 4; ++i) { acc[i][0] = 0ull; acc[i][1] = 0ull; }

    const bool active = (lane < 25);
    const int bi = active ? (lane / 5) : 0;
    const int bj = active ? (lane % 5) : 0;

    for (int tile = 0; tile < NTILE; ++tile) {
        const int t0 = tile * TT;

        // ---- load/convert phase: build m_s, d_s for this tile ----
        if (tid < TT) {
            const int tg = t0 + tid;
            float mt = 0.0f, dt = 0.0f;
            if (tg < NSTEPS) { mt = ((float)tg + 0.5f) * INV; dt = INV; }
            m_s[tid * CPAD]      = mt;    // time channel
            d_s[tid * CPAD]      = dt;
            m_s[tid * CPAD + 19] = 0.0f;  // pad channel
            d_s[tid * CPAD + 19] = 0.0f;
        }
#pragma unroll
        for (int k = 0; k < 9; ++k) {     // 9*256 = 2304 = 128*18 data elements
            const int idx = tid + k * THREADS;
            const int t   = idx / TROW;
            const int c   = idx - t * TROW;
            const int tg  = t0 + t;
            float mv = 0.0f, dv = 0.0f;
            if (tg < NSTEPS) {
                const float a = Xn[tg * TROW + c];
                const float b = Xn[tg * TROW + TROW + c];
                mv = 0.5f * (a + b) - x0_s[c + 1];
                dv = b - a;
            }
            m_s[t * CPAD + c + 1] = mv;
            d_s[t * CPAD + c + 1] = dv;
        }
        __syncthreads();

        // ---- FMA phase: warp w handles t = w, w+8, ..., w+120 ----
        if (active) {
            const float* mp = m_s + w * CPAD + 4 * bi;
            const float* dp = d_s + w * CPAD + 4 * bj;
#pragma unroll 4
            for (int it = 0; it < TT / 8; ++it) {
                const float4 mv = *(const float4*)(mp + it * 8 * CPAD);
                const float4 dv = *(const float4*)(dp + it * 8 * CPAD);
                const unsigned long long d01 = pk2(dv.x, dv.y);
                const unsigned long long d23 = pk2(dv.z, dv.w);
                unsigned long long mm;
                mm = pk2(mv.x, mv.x); ffma2(acc[0][0], mm, d01); ffma2(acc[0][1], mm, d23);
                mm = pk2(mv.y, mv.y); ffma2(acc[1][0], mm, d01); ffma2(acc[1][1], mm, d23);
                mm = pk2(mv.z, mv.z); ffma2(acc[2][0], mm, d01); ffma2(acc[2][1], mm, d23);
                mm = pk2(mv.w, mv.w); ffma2(acc[3][0], mm, d01); ffma2(acc[3][1], mm, d23);
            }
        }
        __syncthreads();  // protect smem before next tile's load overwrites it
    }

    // ---- cross-warp reduction: 8 partial 20x20 tiles -> S2 ----
    float* red = sm;  // 8*400 = 3200 floats, fits in the 5120-float buffer
    if (active) {
#pragma unroll
        for (int ii = 0; ii < 4; ++ii) {
            float lo, hi;
            const int base = w * 400 + (4 * bi + ii) * CPAD + 4 * bj;
            up2(acc[ii][0], lo, hi);
            red[base]     = lo; red[base + 1] = hi;
            up2(acc[ii][1], lo, hi);
            red[base + 2] = lo; red[base + 3] = hi;
        }
    }
    __syncthreads();

    float* o = out + (size_t)n * 380;
    for (int p = tid; p < 400; p += THREADS) {
        float s = red[p]          + red[p + 400]  + red[p + 800]  + red[p + 1200]
                + red[p + 1600]   + red[p + 2000] + red[p + 2400] + red[p + 2800];
        const int i = p / CPAD;
        const int j = p - i * CPAD;
        if (i < 19 && j < 19) o[19 + i * 19 + j] = s;
    }

    // S1: telescoping sums
    if (tid == 0) o[0] = 1.0f;  // time channel: x_t(999) - x_t(0)
    if (tid >= 1 && tid < 19) {
        const int c = tid - 1;
        o[tid] = Xn[(NSTEPS) * TROW + c] - Xn[c];
    }
}

extern "C" void kernel_launch(void* const* d_in, const int* in_sizes, int n_in,
                              void* d_out, int out_size) {
    const float* x = (const float*)d_in[0];
    float* out = (float*)d_out;
    // 128*16 = 2048 sequences, one CTA each
    sig2_kernel<<<2048, THREADS>>>(x, out);
}

// round 3
// speedup vs baseline: 1.2161x; 1.2161x over previous
#include <cuda_runtime.h>
#include <cuda_bf16.h>

// Depth-2 signature via lag-1 Gram reformulation:
//   G_ij = sum_{t=0}^{997+1} x_i(t) x_j(t+1)   (999 steps, x includes time ch 0)
//   S2   = 0.5*(G - G^T) + 0.5*(xT xT^T - x0 x0^T) - x0 (xT - x0)^T
//   S1   = xT - x0
// x: (128,16,1000,18) fp32, time channel = t/999 prepended -> C=19, pad to 20.

#define TT      128
#define ROWS    129           // staged rows per tile (one overlap row)
#define CPAD    20
#define THREADS 256
#define NROWS   1000
#define TROW    18
#define SEQLEN  18000
#define NTILE   8             // 8*128 = 1024 steps >= 999 (tail rows zeroed)
#define LDIT    11            // ceil(129*20/256)

__device__ __forceinline__ unsigned long long pk2(float lo, float hi) {
    unsigned long long r;
    asm("mov.b64 %0, {%1,%2};" : "=l"(r) : "f"(lo), "f"(hi));
    return r;
}
__device__ __forceinline__ void up2(unsigned long long v, float& lo, float& hi) {
    asm("mov.b64 {%0,%1}, %2;" : "=f"(lo), "=f"(hi) : "l"(v));
}
__device__ __forceinline__ void ffma2(unsigned long long& a, unsigned long long x,
                                      unsigned long long y) {
    asm("fma.rn.f32x2 %0, %1, %2, %0;" : "+l"(a) : "l"(x), "l"(y));
}

__global__ __launch_bounds__(THREADS)
void sig2_kernel(const float* __restrict__ x, float* __restrict__ out) {
    const int n = blockIdx.x;
    const float* __restrict__ Xn = x + (size_t)n * SEQLEN;

    __shared__ __align__(16) float xs[2][ROWS * CPAD];   // 2*2580 floats = 20.6 KB
    __shared__ float x0_s[CPAD], xT_s[CPAD];

    const int tid  = threadIdx.x;
    const int w    = tid >> 5;
    const int lane = tid & 31;
    const float INV = 1.0f / 999.0f;

    if (tid < 18) { x0_s[tid + 1] = Xn[tid]; xT_s[tid + 1] = Xn[999 * TROW + tid]; }
    if (tid == 18) { x0_s[0] = 0.0f; xT_s[0] = 1.0f; }
    if (tid == 19) { x0_s[19] = 0.0f; xT_s[19] = 0.0f; }

    const bool active = (lane < 25);
    const int bi = active ? (lane / 5) : 0;
    const int bj = active ? (lane % 5) : 0;

    unsigned long long acc[4][2];
#pragma unroll
    for (int i = 0; i < 4; ++i) { acc[i][0] = 0ull; acc[i][1] = 0ull; }

    // ---- prologue: stage tile 0 ----
    {
        float g[LDIT];
#pragma unroll
        for (int it = 0; it < LDIT; ++it) {
            const int idx = tid + it * THREADS;
            float v = 0.0f;
            if (idx < ROWS * CPAD) {
                const int r = idx / CPAD, c = idx - r * CPAD;
                const int gr = r;                       // tile 0
                if (c == 0)      v = (gr < NROWS) ? (float)gr * INV : 0.0f;
                else if (c < 19) v = (gr < NROWS) ? Xn[gr * TROW + (c - 1)] : 0.0f;
            }
            g[it] = v;
        }
#pragma unroll
        for (int it = 0; it < LDIT; ++it) {
            const int idx = tid + it * THREADS;
            if (idx < ROWS * CPAD) xs[0][idx] = g[it];
        }
    }
    __syncthreads();

    // ---- pipelined main loop ----
    for (int tile = 0; tile < NTILE; ++tile) {
        const int buf = tile & 1;

        // prefetch next tile into registers (LDG overlaps FMA phase below)
        float g[LDIT];
        if (tile + 1 < NTILE) {
            const int base = (tile + 1) * TT;
#pragma unroll
            for (int it = 0; it < LDIT; ++it) {
                const int idx = tid + it * THREADS;
                float v = 0.0f;
                if (idx < ROWS * CPAD) {
                    const int r = idx / CPAD, c = idx - r * CPAD;
                    const int gr = base + r;
                    if (c == 0)      v = (gr < NROWS) ? (float)gr * INV : 0.0f;
                    else if (c < 19) v = (gr < NROWS) ? Xn[gr * TROW + (c - 1)] : 0.0f;
                }
                g[it] = v;
            }
        }

        // FMA phase: warp w handles steps s = w, w+8, ..., w+120 of this tile
        if (active) {
            const float* lp = xs[buf] + w * CPAD + 4 * bi;           // row s  (left, x(t))
            const float* rp = xs[buf] + (w + 1) * CPAD + 4 * bj;     // row s+1 (right, x(t+1))
#pragma unroll 4
            for (int it = 0; it < TT / 8; ++it) {
                const float4 L = *(const float4*)(lp + it * 8 * CPAD);
                const float4 R = *(const float4*)(rp + it * 8 * CPAD);
                const unsigned long long r01 = pk2(R.x, R.y);
                const unsigned long long r23 = pk2(R.z, R.w);
                unsigned long long mm;
                mm = pk2(L.x, L.x); ffma2(acc[0][0], mm, r01); ffma2(acc[0][1], mm, r23);
                mm = pk2(L.y, L.y); ffma2(acc[1][0], mm, r01); ffma2(acc[1][1], mm, r23);
                mm = pk2(L.z, L.z); ffma2(acc[2][0], mm, r01); ffma2(acc[2][1], mm, r23);
                mm = pk2(L.w, L.w); ffma2(acc[3][0], mm, r01); ffma2(acc[3][1], mm, r23);
            }
        }

        // stage next tile into the other buffer
        if (tile + 1 < NTILE) {
#pragma unroll
            for (int it = 0; it < LDIT; ++it) {
                const int idx = tid + it * THREADS;
                if (idx < ROWS * CPAD) xs[buf ^ 1][idx] = g[it];
            }
        }
        __syncthreads();
    }

    // ---- reduction: 8 partial 20x20 G tiles -> G -> S2 ----
    float* red = &xs[0][0];        // 8*400 = 3200 floats
    float* Gs  = red + 3200;       // 400 floats (total 3600 <= 5160)

    if (active) {
#pragma unroll
        for (int ii = 0; ii < 4; ++ii) {
            float a, b, c, d;
            up2(acc[ii][0], a, b);
            up2(acc[ii][1], c, d);
            const int base = w * 400 + (4 * bi + ii) * CPAD + 4 * bj;
            red[base] = a; red[base + 1] = b; red[base + 2] = c; red[base + 3] = d;
        }
    }
    __syncthreads();

    for (int p = tid; p < 400; p += THREADS) {
        Gs[p] = red[p]        + red[p + 400]  + red[p + 800]  + red[p + 1200]
              + red[p + 1600] + red[p + 2000] + red[p + 2400] + red[p + 2800];
    }
    __syncthreads();

    float* o = out + (size_t)n * 380;
    for (int p = tid; p < 400; p += THREADS) {
        const int i = p / CPAD;
        const int j = p - i * CPAD;
        if (i < 19 && j < 19) {
            const float A  = Gs[i * CPAD + j] - Gs[j * CPAD + i];
            const float s2 = 0.5f * A
                           + 0.5f * (xT_s[i] * xT_s[j] - x0_s[i] * x0_s[j])
                           - x0_s[i] * (xT_s[j] - x0_s[j]);
            o[19 + i * 19 + j] = s2;
        }
    }
    if (tid < 19) o[tid] = xT_s[tid] - x0_s[tid];   // S1
}

extern "C" void kernel_launch(void* const* d_in, const int* in_sizes, int n_in,
                              void* d_out, int out_size) {
    const float* x = (const float*)d_in[0];
    float* out = (float*)d_out;
    sig2_kernel<<<2048, THREADS>>>(x, out);
}

// round 4
// speedup vs baseline: 1.5622x; 1.2846x over previous
#include <cuda_runtime.h>
#include <cuda_bf16.h>

// Depth-2 signature via lag-1 Gram reformulation:
//   G_ij = sum_{t=0}^{998} x_i(t) x_j(t+1)   (x includes time channel 0)
//   S2   = 0.5*(G - G^T) + 0.5*(xT xT^T - x0 x0^T) - x0 (xT - x0)^T
//   S1   = xT - x0

#define TT      128
#define ROWS    129
#define CPAD    20
#define THREADS 256
#define NROWS   1000
#define TROW    18
#define SEQLEN  18000
#define NTILE   8
#define V4IT    3             // ceil(576/256) float4 loads per thread per tile

__device__ __forceinline__ unsigned long long pk2(float lo, float hi) {
    unsigned long long r;
    asm("mov.b64 %0, {%1,%2};" : "=l"(r) : "f"(lo), "f"(hi));
    return r;
}
__device__ __forceinline__ void up2(unsigned long long v, float& lo, float& hi) {
    asm("mov.b64 {%0,%1}, %2;" : "=f"(lo), "=f"(hi) : "l"(v));
}
__device__ __forceinline__ void ffma2(unsigned long long& a, unsigned long long x,
                                      unsigned long long y) {
    asm("fma.rn.f32x2 %0, %1, %2, %0;" : "+l"(a) : "l"(x), "l"(y));
}

__global__ __launch_bounds__(THREADS, 4)
void sig2_kernel(const float* __restrict__ x, float* __restrict__ out) {
    const int n = blockIdx.x;
    const float* __restrict__ Xn = x + (size_t)n * SEQLEN;

    __shared__ __align__(16) float xs[2 * ROWS * CPAD];   // 5160 floats = 20.6 KB
    __shared__ float x0_s[CPAD], xT_s[CPAD];

    const int tid  = threadIdx.x;
    const int w    = tid >> 5;
    const int lane = tid & 31;
    const float INV = 1.0f / 999.0f;

    if (tid < 18) { x0_s[tid + 1] = Xn[tid]; xT_s[tid + 1] = Xn[999 * TROW + tid]; }
    if (tid == 18) { x0_s[0] = 0.0f; xT_s[0] = 1.0f; }
    if (tid == 19) { x0_s[19] = 0.0f; xT_s[19] = 0.0f; }

    // pad column (c=19): zero once, both buffers, never touched again
    for (int i = tid; i < 2 * ROWS; i += THREADS) xs[i * CPAD + 19] = 0.0f;

    // ---- precompute tile-invariant staging offsets for the float4 scatter ----
    // iteration it: fi = tid + it*256 (< 576), linear l0 = 4*fi -> (t = l0/18, c = l0%18)
    // smem offset of element e: off0 + e (+2 when crossing into next row: skips pad+time)
    int off0_r[V4IT], wrap_r[V4IT], gof_r[V4IT];
    bool act_r[V4IT];
#pragma unroll
    for (int it = 0; it < V4IT; ++it) {
        const int fi = tid + it * THREADS;
        act_r[it] = (fi < 576);
        const int l0 = 4 * fi;
        const int t  = l0 / TROW, c = l0 - t * TROW;
        off0_r[it] = t * CPAD + c + 1;
        wrap_r[it] = TROW - c;            // elements with e >= wrap go to next row (+2)
        gof_r[it]  = l0;
    }

    const bool active = (lane < 25);
    const int bi = active ? (lane / 5) : 0;
    const int bj = active ? (lane % 5) : 0;

    unsigned long long acc[4][2];
#pragma unroll
    for (int i = 0; i < 4; ++i) { acc[i][0] = 0ull; acc[i][1] = 0ull; }

    // ---- staging helper expanded inline: tile k -> buffer b ----
    // prologue: stage tile 0
    {
        const int gbase = 0;
        float4 f[V4IT];
#pragma unroll
        for (int it = 0; it < V4IT; ++it)
            if (act_r[it]) f[it] = *(const float4*)(Xn + gbase + gof_r[it]);
#pragma unroll
        for (int it = 0; it < V4IT; ++it) {
            if (!act_r[it]) continue;
            const int o = off0_r[it], wr = wrap_r[it];
            xs[o + 0 + (0 >= wr ? 2 : 0)] = f[it].x;
            xs[o + 1 + (1 >= wr ? 2 : 0)] = f[it].y;
            xs[o + 2 + (2 >= wr ? 2 : 0)] = f[it].z;
            xs[o + 3 + (3 >= wr ? 2 : 0)] = f[it].w;
        }
        if (tid < ROWS) xs[tid * CPAD] = (float)tid * INV;                 // time col
        if (tid < TROW) xs[TT * CPAD + 1 + tid] = Xn[TT * TROW + tid];     // overlap row
    }
    __syncthreads();

    for (int tile = 0; tile < NTILE; ++tile) {
        const int buf = tile & 1;
        float* xb = xs + buf * ROWS * CPAD;
        float* xo = xs + (buf ^ 1) * ROWS * CPAD;

        // ---- prefetch next tile into registers ----
        float4 f[V4IT];
        float ovl = 0.0f;
        const int nb = (tile + 1) * TT;              // next tile base row
        if (tile + 1 < NTILE) {
            const int gbase = nb * TROW;
            if (tile + 1 < NTILE - 1) {
#pragma unroll
                for (int it = 0; it < V4IT; ++it)
                    if (act_r[it]) f[it] = *(const float4*)(Xn + gbase + gof_r[it]);
            } else {                                  // last tile: element guards
#pragma unroll
                for (int it = 0; it < V4IT; ++it) {
                    f[it] = make_float4(0.f, 0.f, 0.f, 0.f);
                    if (act_r[it]) {
                        const int g = gbase + gof_r[it];
                        if (g + 3 < SEQLEN) f[it] = *(const float4*)(Xn + g);
                        else {
                            if (g + 0 < SEQLEN) f[it].x = Xn[g + 0];
                            if (g + 1 < SEQLEN) f[it].y = Xn[g + 1];
                            if (g + 2 < SEQLEN) f[it].z = Xn[g + 2];
                            if (g + 3 < SEQLEN) f[it].w = Xn[g + 3];
                        }
                    }
                }
            }
            if (tid < TROW) {
                const int r = nb + TT;
                ovl = (r < NROWS) ? Xn[r * TROW + tid] : 0.0f;
            }
        }

        // ---- FMA phase on current buffer ----
        if (active) {
            const float* lp = xb + w * CPAD + 4 * bi;
            const float* rp = xb + (w + 1) * CPAD + 4 * bj;
#pragma unroll 4
            for (int it = 0; it < TT / 8; ++it) {
                const float4 L = *(const float4*)(lp + it * 8 * CPAD);
                const float4 R = *(const float4*)(rp + it * 8 * CPAD);
                const unsigned long long r01 = pk2(R.x, R.y);
                const unsigned long long r23 = pk2(R.z, R.w);
                unsigned long long mm;
                mm = pk2(L.x, L.x); ffma2(acc[0][0], mm, r01); ffma2(acc[0][1], mm, r23);
                mm = pk2(L.y, L.y); ffma2(acc[1][0], mm, r01); ffma2(acc[1][1], mm, r23);
                mm = pk2(L.z, L.z); ffma2(acc[2][0], mm, r01); ffma2(acc[2][1], mm, r23);
                mm = pk2(L.w, L.w); ffma2(acc[3][0], mm, r01); ffma2(acc[3][1], mm, r23);
            }
        }

        // ---- commit staged tile ----
        if (tile + 1 < NTILE) {
#pragma unroll
            for (int it = 0; it < V4IT; ++it) {
                if (!act_r[it]) continue;
                const int o = off0_r[it], wr = wrap_r[it];
                xo[o + 0 + (0 >= wr ? 2 : 0)] = f[it].x;
                xo[o + 1 + (1 >= wr ? 2 : 0)] = f[it].y;
                xo[o + 2 + (2 >= wr ? 2 : 0)] = f[it].z;
                xo[o + 3 + (3 >= wr ? 2 : 0)] = f[it].w;
            }
            if (tid < ROWS) {
                const int r = nb + tid;
                xo[tid * CPAD] = (r < NROWS) ? (float)r * INV : 0.0f;
            }
            if (tid < TROW) xo[TT * CPAD + 1 + tid] = ovl;
        }
        __syncthreads();
    }

    // ---- reduction: 8 partial 20x20 G tiles -> G -> S2 ----
    float* red = xs;               // 3200 floats
    float* Gs  = xs + 3200;        // 400 floats (total 3600 <= 5160)

    if (active) {
#pragma unroll
        for (int ii = 0; ii < 4; ++ii) {
            float a, b, c, d;
            up2(acc[ii][0], a, b);
            up2(acc[ii][1], c, d);
            const int base = w * 400 + (4 * bi + ii) * CPAD + 4 * bj;
            red[base] = a; red[base + 1] = b; red[base + 2] = c; red[base + 3] = d;
        }
    }
    __syncthreads();

    for (int p = tid; p < 400; p += THREADS) {
        Gs[p] = red[p]        + red[p + 400]  + red[p + 800]  + red[p + 1200]
              + red[p + 1600] + red[p + 2000] + red[p + 2400] + red[p + 2800];
    }
    __syncthreads();

    float* o = out + (size_t)n * 380;
    for (int p = tid; p < 400; p += THREADS) {
        const int i = p / CPAD;
        const int j = p - i * CPAD;
        if (i < 19 && j < 19) {
            const float A  = Gs[i * CPAD + j] - Gs[j * CPAD + i];
            o[19 + i * 19 + j] = 0.5f * A
                               + 0.5f * (xT_s[i] * xT_s[j] - x0_s[i] * x0_s[j])
                               - x0_s[i] * (xT_s[j] - x0_s[j]);
        }
    }
    if (tid < 19) o[tid] = xT_s[tid] - x0_s[tid];   // S1
}

extern "C" void kernel_launch(void* const* d_in, const int* in_sizes, int n_in,
                              void* d_out, int out_size) {
    const float* x = (const float*)d_in[0];
    float* out = (float*)d_out;
    sig2_kernel<<<2048, THREADS>>>(x, out);
}

// round 5
// speedup vs baseline: 1.8236x; 1.1674x over previous
#include <cuda_runtime.h>
#include <cuda_bf16.h>

// Depth-2 signature via lag-1 Gram reformulation:
//   G_ij = sum_{t=0}^{998} x_i(t) x_j(t+1)   (x includes time channel 0)
//   S2   = 0.5*(G - G^T) + 0.5*(xT xT^T - x0 x0^T) - x0 (xT - x0)^T
//   S1   = xT - x0
// Mainloop: pair-tiled (lane owns tiles (bi,bj) AND (bj,bi)), contiguous-step
// row reuse: per new step only the new row's two slices are loaded.

#define TT      128
#define ROWS    129
#define CPAD    20
#define THREADS 256
#define NROWS   1000
#define TROW    18
#define SEQLEN  18000
#define NTILE   8
#define V4IT    3

// pair tables, 4 bits per pair index p=0..14 (p<5: diag)
#define BI_PACK 0x322111000043210ull
#define BJ_PACK 0x443432432143210ull

__device__ __forceinline__ unsigned long long pk2(float lo, float hi) {
    unsigned long long r;
    asm("mov.b64 %0, {%1,%2};" : "=l"(r) : "f"(lo), "f"(hi));
    return r;
}
__device__ __forceinline__ void up2(unsigned long long v, float& lo, float& hi) {
    asm("mov.b64 {%0,%1}, %2;" : "=f"(lo), "=f"(hi) : "l"(v));
}
__device__ __forceinline__ void ffma2(unsigned long long& a, unsigned long long x,
                                      unsigned long long y) {
    asm("fma.rn.f32x2 %0, %1, %2, %0;" : "+l"(a) : "l"(x), "l"(y));
}

#define OUTER(acc, Lv, Rv) do {                                              \
    const unsigned long long r01 = pk2((Rv).x, (Rv).y);                      \
    const unsigned long long r23 = pk2((Rv).z, (Rv).w);                      \
    unsigned long long mm;                                                   \
    mm = pk2((Lv).x, (Lv).x); ffma2(acc[0][0], mm, r01); ffma2(acc[0][1], mm, r23); \
    mm = pk2((Lv).y, (Lv).y); ffma2(acc[1][0], mm, r01); ffma2(acc[1][1], mm, r23); \
    mm = pk2((Lv).z, (Lv).z); ffma2(acc[2][0], mm, r01); ffma2(acc[2][1], mm, r23); \
    mm = pk2((Lv).w, (Lv).w); ffma2(acc[3][0], mm, r01); ffma2(acc[3][1], mm, r23); \
} while (0)

__global__ __launch_bounds__(THREADS, 3)
void sig2_kernel(const float* __restrict__ x, float* __restrict__ out) {
    const int n = blockIdx.x;
    const float* __restrict__ Xn = x + (size_t)n * SEQLEN;

    __shared__ __align__(16) float xs[2 * ROWS * CPAD];   // 20.6 KB
    __shared__ float x0_s[CPAD], xT_s[CPAD];

    const int tid  = threadIdx.x;
    const int w    = tid >> 5;
    const int lane = tid & 31;
    const float INV = 1.0f / 999.0f;

    if (tid < 18) { x0_s[tid + 1] = Xn[tid]; xT_s[tid + 1] = Xn[999 * TROW + tid]; }
    if (tid == 18) { x0_s[0] = 0.0f; xT_s[0] = 1.0f; }
    if (tid == 19) { x0_s[19] = 0.0f; xT_s[19] = 0.0f; }

    // pad column: zero once in both buffers
    for (int i = tid; i < 2 * ROWS; i += THREADS) xs[i * CPAD + 19] = 0.0f;

    // tile-invariant staging offsets (float4 gather -> padded smem scatter)
    int off0_r[V4IT], wrap_r[V4IT], gof_r[V4IT];
    bool act_r[V4IT];
#pragma unroll
    for (int it = 0; it < V4IT; ++it) {
        const int fi = tid + it * THREADS;
        act_r[it] = (fi < 576);
        const int l0 = 4 * fi;
        const int t  = l0 / TROW, c = l0 - t * TROW;
        off0_r[it] = t * CPAD + c + 1;
        wrap_r[it] = TROW - c;
        gof_r[it]  = l0;
    }

    // lane's tile pair
    const int p  = lane & 15;
    const int bi = (int)((BI_PACK >> (4 * p)) & 15ull);
    const int bj = (int)((BJ_PACK >> (4 * p)) & 15ull);
    const int half = lane >> 4;
    const bool factive = (p < 15);
    const int rowoff = 8 * (2 * w + half) * CPAD;

    unsigned long long accA[4][2], accB[4][2];
#pragma unroll
    for (int i = 0; i < 4; ++i) {
        accA[i][0] = 0ull; accA[i][1] = 0ull;
        accB[i][0] = 0ull; accB[i][1] = 0ull;
    }

    // ---- prologue: stage tile 0 ----
    {
        float4 f[V4IT];
#pragma unroll
        for (int it = 0; it < V4IT; ++it)
            if (act_r[it]) f[it] = *(const float4*)(Xn + gof_r[it]);
#pragma unroll
        for (int it = 0; it < V4IT; ++it) {
            if (!act_r[it]) continue;
            const int o = off0_r[it], wr = wrap_r[it];
            xs[o + 0 + (0 >= wr ? 2 : 0)] = f[it].x;
            xs[o + 1 + (1 >= wr ? 2 : 0)] = f[it].y;
            xs[o + 2 + (2 >= wr ? 2 : 0)] = f[it].z;
            xs[o + 3 + (3 >= wr ? 2 : 0)] = f[it].w;
        }
        if (tid < ROWS) xs[tid * CPAD] = (float)tid * INV;
        if (tid < TROW) xs[TT * CPAD + 1 + tid] = Xn[TT * TROW + tid];
    }
    __syncthreads();

    for (int tile = 0; tile < NTILE; ++tile) {
        const int buf = tile & 1;
        const float* xb = xs + buf * ROWS * CPAD;
        float* xo = xs + (buf ^ 1) * ROWS * CPAD;

        // ---- prefetch next tile into registers ----
        float4 f[V4IT];
        float ovl = 0.0f;
        const int nb = (tile + 1) * TT;
        if (tile + 1 < NTILE) {
            const int gbase = nb * TROW;
            if (tile + 1 < NTILE - 1) {
#pragma unroll
                for (int it = 0; it < V4IT; ++it)
                    if (act_r[it]) f[it] = *(const float4*)(Xn + gbase + gof_r[it]);
            } else {
#pragma unroll
                for (int it = 0; it < V4IT; ++it) {
                    f[it] = make_float4(0.f, 0.f, 0.f, 0.f);
                    if (act_r[it]) {
                        const int g = gbase + gof_r[it];
                        if (g + 3 < SEQLEN) f[it] = *(const float4*)(Xn + g);
                        else {
                            if (g + 0 < SEQLEN) f[it].x = Xn[g + 0];
                            if (g + 1 < SEQLEN) f[it].y = Xn[g + 1];
                            if (g + 2 < SEQLEN) f[it].z = Xn[g + 2];
                            if (g + 3 < SEQLEN) f[it].w = Xn[g + 3];
                        }
                    }
                }
            }
            if (tid < TROW) {
                const int r = nb + TT;
                ovl = (r < NROWS) ? Xn[r * TROW + tid] : 0.0f;
            }
        }

        // ---- FMA phase: 8 contiguous steps per (warp, half), row reuse ----
        if (factive) {
            const float* pa = xb + rowoff + 4 * bi;
            const float* pb = xb + rowoff + 4 * bj;
            float4 La = *(const float4*)pa;
            float4 Lb = *(const float4*)pb;
#pragma unroll
            for (int k = 1; k <= 7; k += 2) {
                const float4 Ra = *(const float4*)(pa + k * CPAD);
                const float4 Rb = *(const float4*)(pb + k * CPAD);
                OUTER(accA, La, Rb);
                OUTER(accB, Lb, Ra);
                const float4 Sa = *(const float4*)(pa + (k + 1) * CPAD);
                const float4 Sb = *(const float4*)(pb + (k + 1) * CPAD);
                OUTER(accA, Ra, Sb);
                OUTER(accB, Rb, Sa);
                La = Sa; Lb = Sb;
            }
        }

        // ---- commit staged tile ----
        if (tile + 1 < NTILE) {
#pragma unroll
            for (int it = 0; it < V4IT; ++it) {
                if (!act_r[it]) continue;
                const int o = off0_r[it], wr = wrap_r[it];
                xo[o + 0 + (0 >= wr ? 2 : 0)] = f[it].x;
                xo[o + 1 + (1 >= wr ? 2 : 0)] = f[it].y;
                xo[o + 2 + (2 >= wr ? 2 : 0)] = f[it].z;
                xo[o + 3 + (3 >= wr ? 2 : 0)] = f[it].w;
            }
            if (tid < ROWS) {
                const int r = nb + tid;
                xo[tid * CPAD] = (r < NROWS) ? (float)r * INV : 0.0f;
            }
            if (tid < TROW) xo[TT * CPAD + 1 + tid] = ovl;
        }
        __syncthreads();
    }

    // ---- combine halves (pairs align across half-warps) ----
    float outA[4][4], outB[4][4];
#pragma unroll
    for (int ii = 0; ii < 4; ++ii) {
#pragma unroll
        for (int q = 0; q < 2; ++q) {
            const unsigned long long oA = __shfl_xor_sync(0xffffffffu, accA[ii][q], 16);
            const unsigned long long oB = __shfl_xor_sync(0xffffffffu, accB[ii][q], 16);
            float a0, a1, c0, c1;
            up2(accA[ii][q], a0, a1); up2(oA, c0, c1);
            outA[ii][2 * q] = a0 + c0; outA[ii][2 * q + 1] = a1 + c1;
            up2(accB[ii][q], a0, a1); up2(oB, c0, c1);
            outB[ii][2 * q] = a0 + c0; outB[ii][2 * q + 1] = a1 + c1;
        }
    }

    // ---- reduction: 8 warp-partial 20x20 G tiles -> G -> S2 ----
    float* red = xs;
    float* Gs  = xs + 3200;

    if (lane < 15) {
#pragma unroll
        for (int ii = 0; ii < 4; ++ii)
#pragma unroll
            for (int jj = 0; jj < 4; ++jj)
                red[w * 400 + (4 * bi + ii) * CPAD + 4 * bj + jj] = outA[ii][jj];
        if (p >= 5) {
#pragma unroll
            for (int ii = 0; ii < 4; ++ii)
#pragma unroll
                for (int jj = 0; jj < 4; ++jj)
                    red[w * 400 + (4 * bj + ii) * CPAD + 4 * bi + jj] = outB[ii][jj];
        }
    }
    __syncthreads();

    for (int pp = tid; pp < 400; pp += THREADS) {
        Gs[pp] = red[pp]        + red[pp + 400]  + red[pp + 800]  + red[pp + 1200]
               + red[pp + 1600] + red[pp + 2000] + red[pp + 2400] + red[pp + 2800];
    }
    __syncthreads();

    float* o = out + (size_t)n * 380;
    for (int pp = tid; pp < 400; pp += THREADS) {
        const int i = pp / CPAD;
        const int j = pp - i * CPAD;
        if (i < 19 && j < 19) {
            const float A = Gs[i * CPAD + j] - Gs[j * CPAD + i];
            o[19 + i * 19 + j] = 0.5f * A
                               + 0.5f * (xT_s[i] * xT_s[j] - x0_s[i] * x0_s[j])
                               - x0_s[i] * (xT_s[j] - x0_s[j]);
        }
    }
    if (tid < 19) o[tid] = xT_s[tid] - x0_s[tid];   // S1
}

extern "C" void kernel_launch(void* const* d_in, const int* in_sizes, int n_in,
                              void* d_out, int out_size) {
    const float* x = (const float*)d_in[0];
    float* out = (float*)d_out;
    sig2_kernel<<<2048, THREADS>>>(x, out);
}

// round 6
// speedup vs baseline: 2.3039x; 1.2634x over previous
#include <cuda_runtime.h>
#include <cuda_bf16.h>

// Depth-2 signature via Levy-area wedge pairing:
//   A = G - G^T = sum_s u_s v_s^T - (.)^T,  u_s = x(2s)-x(2s+2), v_s = x(2s+1)
//   (rows > 999 treated as zero; 512 wedge slots = 8 tiles x 64)
//   S2 = 0.5*A + 0.5*(xT xT^T - x0 x0^T) - x0 (xT - x0)^T,  S1 = xT - x0
// Padded channel layout per row: [time, pad, d0..d17]  (CP=20)

#define THREADS 256
#define NROWS   1000
#define TROW    18
#define SEQLEN  18000
#define NTILE   8
#define CP      20
#define EROWS   65
#define VOFF    1300          // 65*20, V region base within a buffer
#define BUF     2580          // (65+64)*20 floats per buffer
#define SPANF4  581           // ceil(129*18/4) float4 per tile span
#define V4IT    3

__device__ __forceinline__ unsigned long long pk2(float lo, float hi) {
    unsigned long long r;
    asm("mov.b64 %0, {%1,%2};" : "=l"(r) : "f"(lo), "f"(hi));
    return r;
}
__device__ __forceinline__ void up2(unsigned long long v, float& lo, float& hi) {
    asm("mov.b64 {%0,%1}, %2;" : "=f"(lo), "=f"(hi) : "l"(v));
}
__device__ __forceinline__ void ffma2(unsigned long long& a, unsigned long long x,
                                      unsigned long long y) {
    asm("fma.rn.f32x2 %0, %1, %2, %0;" : "+l"(a) : "l"(x), "l"(y));
}

__global__ __launch_bounds__(THREADS, 3)
void sig2_kernel(const float* __restrict__ x, float* __restrict__ out) {
    const int n = blockIdx.x;
    const float* __restrict__ Xn = x + (size_t)n * SEQLEN;

    __shared__ __align__(16) float xs[2 * BUF];    // 20.6 KB
    __shared__ float x0_s[CP], xT_s[CP];

    const int tid  = threadIdx.x;
    const int w    = tid >> 5;
    const int lane = tid & 31;
    const float INV = 1.0f / 999.0f;

    if (tid < 18) { x0_s[tid + 1] = Xn[tid]; xT_s[tid + 1] = Xn[999 * TROW + tid]; }
    if (tid == 18) { x0_s[0] = 0.0f; xT_s[0] = 1.0f; }

    // pad column (padded index 1) of all 258 rows across both buffers: zero once
    for (int i = tid; i < 2 * (EROWS + 64); i += THREADS) xs[i * CP + 1] = 0.0f;

    // ---- tile-invariant staging routing (float4 -> two parity-routed float2) ----
    int off_a[V4IT], off_b[V4IT], gof[V4IT];
    bool act_a[V4IT], act_b[V4IT];
#pragma unroll
    for (int it = 0; it < V4IT; ++it) {
        const int fi = tid + it * THREADS;
        const bool slot = (fi < SPANF4);
        const int l0 = 4 * fi;         // pair a: elements l0,l0+1
        const int l1 = l0 + 2;         // pair b
        const int r0 = l0 / TROW, c0 = l0 - r0 * TROW;
        const int r1 = l1 / TROW, c1 = l1 - r1 * TROW;
        act_a[it] = slot && (r0 <= 128);
        act_b[it] = slot && (r1 <= 128);
        off_a[it] = (r0 & 1) ? (VOFF + ((r0 - 1) >> 1) * CP + c0 + 2)
                             : ((r0 >> 1) * CP + c0 + 2);
        off_b[it] = (r1 & 1) ? (VOFF + ((r1 - 1) >> 1) * CP + c1 + 2)
                             : ((r1 >> 1) * CP + c1 + 2);
        gof[it] = l0;
    }

    const bool mact = (lane < 25);
    const int bi = lane / 5;
    const int bj = lane - 5 * bi;

    unsigned long long acc[4][2];
#pragma unroll
    for (int i = 0; i < 4; ++i) { acc[i][0] = 0ull; acc[i][1] = 0ull; }

    // ---- prologue: stage tile 0 into buffer 0 ----
    {
        float4 f[V4IT];
#pragma unroll
        for (int it = 0; it < V4IT; ++it) {
            f[it] = make_float4(0.f, 0.f, 0.f, 0.f);
            if (act_a[it] || act_b[it]) f[it] = *(const float4*)(Xn + gof[it]);
        }
#pragma unroll
        for (int it = 0; it < V4IT; ++it) {
            if (act_a[it]) *(float2*)(xs + off_a[it]) = make_float2(f[it].x, f[it].y);
            if (act_b[it]) *(float2*)(xs + off_b[it]) = make_float2(f[it].z, f[it].w);
        }
        if (tid < EROWS) xs[tid * CP] = (float)(2 * tid) * INV;           // E time
        if (tid < 64)    xs[VOFF + tid * CP] = (float)(2 * tid + 1) * INV; // V time
    }
    __syncthreads();

    for (int tile = 0; tile < NTILE; ++tile) {
        const int buf = tile & 1;
        const float* xb = xs + buf * BUF;
        float* xo = xs + (buf ^ 1) * BUF;
        const int nt = tile + 1;

        // ---- prefetch next tile's span into registers ----
        float4 f[V4IT];
        if (nt < NTILE) {
            const int gbase = nt * 2304;        // 128*18 elements per tile
            if (nt < NTILE - 1) {
#pragma unroll
                for (int it = 0; it < V4IT; ++it) {
                    f[it] = make_float4(0.f, 0.f, 0.f, 0.f);
                    if (act_a[it] || act_b[it]) f[it] = *(const float4*)(Xn + gbase + gof[it]);
                }
            } else {
#pragma unroll
                for (int it = 0; it < V4IT; ++it) {
                    f[it] = make_float4(0.f, 0.f, 0.f, 0.f);
                    if (act_a[it] || act_b[it]) {
                        const int g = gbase + gof[it];
                        if (g + 3 < SEQLEN) f[it] = *(const float4*)(Xn + g);
                        else {
                            if (g + 0 < SEQLEN) f[it].x = Xn[g + 0];
                            if (g + 1 < SEQLEN) f[it].y = Xn[g + 1];
                            if (g + 2 < SEQLEN) f[it].z = Xn[g + 2];
                            if (g + 3 < SEQLEN) f[it].w = Xn[g + 3];
                        }
                    }
                }
            }
        }

        // ---- mainloop: warp w handles wedges l = 8w .. 8w+7 of this tile ----
        if (mact) {
            const float* Eb = xb + (8 * w) * CP + 4 * bi;
            const float* Vb = xb + VOFF + (8 * w) * CP + 4 * bj;
            float4 Ec = *(const float4*)Eb;
#pragma unroll
            for (int k = 0; k < 8; ++k) {
                const float4 En = *(const float4*)(Eb + (k + 1) * CP);
                const float4 Vv = *(const float4*)(Vb + k * CP);
                const unsigned long long v01 = pk2(Vv.x, Vv.y);
                const unsigned long long v23 = pk2(Vv.z, Vv.w);
                const float u0 = Ec.x - En.x;
                const float u1 = Ec.y - En.y;
                const float u2 = Ec.z - En.z;
                const float u3 = Ec.w - En.w;
                unsigned long long mm;
                mm = pk2(u0, u0); ffma2(acc[0][0], mm, v01); ffma2(acc[0][1], mm, v23);
                mm = pk2(u1, u1); ffma2(acc[1][0], mm, v01); ffma2(acc[1][1], mm, v23);
                mm = pk2(u2, u2); ffma2(acc[2][0], mm, v01); ffma2(acc[2][1], mm, v23);
                mm = pk2(u3, u3); ffma2(acc[3][0], mm, v01); ffma2(acc[3][1], mm, v23);
                Ec = En;
            }
        }

        // ---- commit staged tile ----
        if (nt < NTILE) {
#pragma unroll
            for (int it = 0; it < V4IT; ++it) {
                if (act_a[it]) *(float2*)(xo + off_a[it]) = make_float2(f[it].x, f[it].y);
                if (act_b[it]) *(float2*)(xo + off_b[it]) = make_float2(f[it].z, f[it].w);
            }
            if (tid < EROWS) {
                const int r = 128 * nt + 2 * tid;
                xo[tid * CP] = (r <= 999) ? (float)r * INV : 0.0f;
            }
            if (tid < 64) {
                const int r = 128 * nt + 2 * tid + 1;
                xo[VOFF + tid * CP] = (r <= 999) ? (float)r * INV : 0.0f;
            }
        }
        __syncthreads();
    }

    // ---- reduction: 8 warp-partial 20x20 P tiles -> P ----
    float* red = xs;                // 3200 floats
    float* Ps  = xs + 3200;         // 400 floats
    if (mact) {
#pragma unroll
        for (int ii = 0; ii < 4; ++ii) {
            float a, b, c, d;
            up2(acc[ii][0], a, b);
            up2(acc[ii][1], c, d);
            const int base = w * 400 + (4 * bi + ii) * CP + 4 * bj;
            red[base] = a; red[base + 1] = b; red[base + 2] = c; red[base + 3] = d;
        }
    }
    __syncthreads();

    for (int pp = tid; pp < 400; pp += THREADS) {
        Ps[pp] = red[pp]        + red[pp + 400]  + red[pp + 800]  + red[pp + 1200]
               + red[pp + 1600] + red[pp + 2000] + red[pp + 2400] + red[pp + 2800];
    }
    __syncthreads();

    // ---- epilogue: A = P - P^T, add boundary terms ----
    float* o = out + (size_t)n * 380;
    for (int pp = tid; pp < 361; pp += THREADS) {
        const int fi = pp / 19;
        const int fj = pp - 19 * fi;
        const int i2 = fi ? fi + 1 : 0;     // final index -> padded column
        const int j2 = fj ? fj + 1 : 0;
        const float A = Ps[i2 * CP + j2] - Ps[j2 * CP + i2];
        o[19 + pp] = 0.5f * A
                   + 0.5f * (xT_s[fi] * xT_s[fj] - x0_s[fi] * x0_s[fj])
                   - x0_s[fi] * (xT_s[fj] - x0_s[fj]);
    }
    if (tid < 19) o[tid] = xT_s[tid] - x0_s[tid];   // S1
}

extern "C" void kernel_launch(void* const* d_in, const int* in_sizes, int n_in,
                              void* d_out, int out_size) {
    const float* x = (const float*)d_in[0];
    float* out = (float*)d_out;
    sig2_kernel<<<2048, THREADS>>>(x, out);
}

// round 8
// speedup vs baseline: 2.4749x; 1.0742x over previous
#include <cuda_runtime.h>
#include <cuda_bf16.h>

// Depth-2 signature, Levy-area wedge pairing + TMA bulk staging (raw layout):
//   A = sum_s (x(2s)-x(2s+2)) ^ x(2s+1)   (rows >= 1000 treated as zero)
//   S2 = 0.5*(A) + 0.5*(xT xT^T - x0 x0^T) - x0 (xT - x0)^T,  S1 = xT - x0
// Time channel synthesized analytically (not stored):
//   P[0][j] = -(2/999)*sum_s v_j + (1000/999)*x999_j ;  P[j][0] = (1/999)*sum_s u_j*(2s+1)
// (R7 resubmit: R6 bench was an infra failure — container died, no kernel verdict.)

#define THREADS 256
#define TROW    18
#define SEQLEN  18000
#define NTILE   8
#define TILEB   9296          // bytes per full tile copy (129 rows * 72B, padded to 16)
#define LASTB   7488          // tile 7: rows 896..999 exactly
#define BUFF    2336          // floats per buffer (9344 B)
#define ZSTART  1872          // LASTB/4: first zero float of buffer 1 tail

__device__ __forceinline__ unsigned long long pk2(float lo, float hi) {
    unsigned long long r;
    asm("mov.b64 %0, {%1,%2};" : "=l"(r) : "f"(lo), "f"(hi));
    return r;
}
__device__ __forceinline__ void up2(unsigned long long v, float& lo, float& hi) {
    asm("mov.b64 {%0,%1}, %2;" : "=f"(lo), "=f"(hi) : "l"(v));
}
__device__ __forceinline__ void ffma2(unsigned long long& a, unsigned long long x,
                                      unsigned long long y) {
    asm("fma.rn.f32x2 %0, %1, %2, %0;" : "+l"(a) : "l"(x), "l"(y));
}
__device__ __forceinline__ void mbar_init(unsigned mb, unsigned cnt) {
    asm volatile("mbarrier.init.shared.b64 [%0], %1;" :: "r"(mb), "r"(cnt) : "memory");
}
__device__ __forceinline__ void mbar_expect_tx(unsigned mb, unsigned bytes) {
    asm volatile("mbarrier.arrive.expect_tx.shared.b64 _, [%0], %1;"
                 :: "r"(mb), "r"(bytes) : "memory");
}
__device__ __forceinline__ void bulk_g2s(unsigned dst, const void* src,
                                         unsigned bytes, unsigned mb) {
    asm volatile("cp.async.bulk.shared::cluster.global.mbarrier::complete_tx::bytes "
                 "[%0], [%1], %2, [%3];"
                 :: "r"(dst), "l"(src), "r"(bytes), "r"(mb) : "memory");
}
__device__ __forceinline__ void mbar_wait(unsigned mb, unsigned parity) {
    unsigned done;
    asm volatile(
        "{\n\t.reg .pred p;\n\t"
        "mbarrier.try_wait.parity.acquire.cta.shared::cta.b64 p, [%1], %2;\n\t"
        "selp.b32 %0, 1, 0, p;\n\t}"
        : "=r"(done) : "r"(mb), "r"(parity) : "memory");
    if (!done) {
        asm volatile(
            "{\n\t.reg .pred P1;\n\t"
            "WL_%=:\n\t"
            "mbarrier.try_wait.parity.acquire.cta.shared::cta.b64 P1, [%0], %1, 0x989680;\n\t"
            "@P1 bra.uni WD_%=;\n\t"
            "bra.uni WL_%=;\n\t"
            "WD_%=:\n\t}"
            :: "r"(mb), "r"(parity) : "memory");
    }
}

__global__ __launch_bounds__(THREADS, 3)
void sig2_kernel(const float* __restrict__ x, float* __restrict__ out) {
    const int n = blockIdx.x;
    const float* __restrict__ Xn = x + (size_t)n * SEQLEN;

    __shared__ __align__(16) float xs[2 * BUFF];     // 18.7 KB
    __shared__ float x0_s[20], xT_s[20];
    __shared__ __align__(8) unsigned long long mbar[2];

    const int tid  = threadIdx.x;
    const int w    = tid >> 5;
    const int lane = tid & 31;
    const float INV = 1.0f / 999.0f;

    if (tid < 18) { x0_s[tid + 1] = Xn[tid]; xT_s[tid + 1] = Xn[999 * TROW + tid]; }
    if (tid == 18) { x0_s[0] = 0.0f; xT_s[0] = 1.0f; }

    const unsigned mb0 = (unsigned)__cvta_generic_to_shared(&mbar[0]);
    const unsigned mb1 = (unsigned)__cvta_generic_to_shared(&mbar[1]);
    const unsigned sb0 = (unsigned)__cvta_generic_to_shared(xs);
    const unsigned sb1 = (unsigned)__cvta_generic_to_shared(xs + BUFF);

    if (tid == 0) { mbar_init(mb0, 1); mbar_init(mb1, 1); }
    __syncthreads();

    if (tid == 0) { mbar_expect_tx(mb0, TILEB); bulk_g2s(sb0, Xn, TILEB, mb0); }

    const bool mact = (lane < 25);
    const int bi = lane / 5;
    const int bj = lane - 5 * bi;
    const bool do_sv = mact && (bi == 0);
    const bool do_su = mact && (bj == 0);

    unsigned long long acc[4][2];
#pragma unroll
    for (int i = 0; i < 4; ++i) { acc[i][0] = 0ull; acc[i][1] = 0ull; }
    float sv[4] = {0.f, 0.f, 0.f, 0.f};
    float su[4] = {0.f, 0.f, 0.f, 0.f};

    for (int t = 0; t < NTILE; ++t) {
        const int nt = t + 1;
        if (tid == 0 && nt < NTILE) {
            const unsigned bytes = (nt == NTILE - 1) ? LASTB : TILEB;
            const unsigned mb = (nt & 1) ? mb1 : mb0;
            const unsigned db = (nt & 1) ? sb1 : sb0;
            mbar_expect_tx(mb, bytes);
            bulk_g2s(db, Xn + nt * 2304, bytes, mb);
        }
        if (t == 6) {   // zero tail of buffer 1 (rows >= 1000) before tile 7 is consumed
            for (int i = tid; i < BUFF - ZSTART; i += THREADS) xs[BUFF + ZSTART + i] = 0.0f;
        }

        mbar_wait((t & 1) ? mb1 : mb0, (t >> 1) & 1);

        if (mact) {
            const float* bb = xs + (t & 1) * BUFF;
            const float* Ep = bb + 288 * w + 4 * bi;        // even rows, 16B aligned
            const float* Vp = bb + 288 * w + 18 + 4 * bj;   // odd rows, 8B aligned
            float4 Ec = *(const float4*)Ep;
            float ws = (float)(128 * t + 16 * w + 1);        // 2s+1
#pragma unroll
            for (int k = 0; k < 8; ++k) {
                const float4 En = *(const float4*)(Ep + 36 * (k + 1));
                const float2 Va = *(const float2*)(Vp + 36 * k);
                const float2 Vb = *(const float2*)(Vp + 36 * k + 2);
                const float u0 = Ec.x - En.x, u1 = Ec.y - En.y;
                const float u2 = Ec.z - En.z, u3 = Ec.w - En.w;
                const unsigned long long v01 = pk2(Va.x, Va.y);
                const unsigned long long v23 = pk2(Vb.x, Vb.y);
                unsigned long long mm;
                mm = pk2(u0, u0); ffma2(acc[0][0], mm, v01); ffma2(acc[0][1], mm, v23);
                mm = pk2(u1, u1); ffma2(acc[1][0], mm, v01); ffma2(acc[1][1], mm, v23);
                mm = pk2(u2, u2); ffma2(acc[2][0], mm, v01); ffma2(acc[2][1], mm, v23);
                mm = pk2(u3, u3); ffma2(acc[3][0], mm, v01); ffma2(acc[3][1], mm, v23);
                if (do_sv) { sv[0] += Va.x; sv[1] += Va.y; sv[2] += Vb.x; sv[3] += Vb.y; }
                if (do_su) { su[0] += u0 * ws; su[1] += u1 * ws;
                             su[2] += u2 * ws; su[3] += u3 * ws; }
                ws += 2.0f;
                Ec = En;
            }
        }
        __syncthreads();
    }

    // ---- reduction: 8 warp-partials (20x20 P tile + sv[20] + su[20]) ----
    float* red = xs;                 // 8*440 = 3520 floats
    float* Ps  = xs + 3520;          // 440 floats (total 3960 <= 4672)

    if (mact) {
#pragma unroll
        for (int ii = 0; ii < 4; ++ii) {
            float a, b, c, d;
            up2(acc[ii][0], a, b);
            up2(acc[ii][1], c, d);
            const int base = w * 440 + (4 * bi + ii) * 20 + 4 * bj;
            red[base] = a; red[base + 1] = b; red[base + 2] = c; red[base + 3] = d;
        }
    }
    if (do_sv) {
#pragma unroll
        for (int q = 0; q < 4; ++q) red[w * 440 + 400 + 4 * bj + q] = sv[q];
    }
    if (do_su) {
#pragma unroll
        for (int q = 0; q < 4; ++q) red[w * 440 + 420 + 4 * bi + q] = su[q];
    }
    __syncthreads();

    for (int p = tid; p < 440; p += THREADS) {
        Ps[p] = red[p]         + red[p + 440]  + red[p + 880]  + red[p + 1320]
              + red[p + 1760]  + red[p + 2200] + red[p + 2640] + red[p + 3080];
    }
    __syncthreads();

    const float* SV = Ps + 400;
    const float* SU = Ps + 420;

    // ---- epilogue: A = P - P^T (data block + analytic time row/col) ----
    float* o = out + (size_t)n * 380;
    for (int pp = tid; pp < 361; pp += THREADS) {
        const int fi = pp / 19;
        const int fj = pp - 19 * fi;
        float A;
        if (fi > 0 && fj > 0) {
            A = Ps[(fi - 1) * 20 + (fj - 1)] - Ps[(fj - 1) * 20 + (fi - 1)];
        } else if (fi == 0 && fj == 0) {
            A = 0.0f;
        } else if (fi == 0) {
            const int c = fj - 1;
            const float P0j = -2.0f * INV * SV[c] + 1000.0f * INV * xT_s[fj];
            const float Pj0 = INV * SU[c];
            A = P0j - Pj0;
        } else {
            const int c = fi - 1;
            const float P0i = -2.0f * INV * SV[c] + 1000.0f * INV * xT_s[fi];
            const float Pi0 = INV * SU[c];
            A = Pi0 - P0i;
        }
        o[19 + pp] = 0.5f * A
                   + 0.5f * (xT_s[fi] * xT_s[fj] - x0_s[fi] * x0_s[fj])
                   - x0_s[fi] * (xT_s[fj] - x0_s[fj]);
    }
    if (tid < 19) o[tid] = xT_s[tid] - x0_s[tid];   // S1
}

extern "C" void kernel_launch(void* const* d_in, const int* in_sizes, int n_in,
                              void* d_out, int out_size) {
    const float* x = (const float*)d_in[0];
    float* out = (float*)d_out;
    sig2_kernel<<<2048, THREADS>>>(x, out);
}